// round 13
// baseline (speedup 1.0000x reference)
#include <cuda_runtime.h>
#include <cstdint>

// MoE router: logits = x @ W^T via mma.sync tf32 3-term split (3xTF32).
// hi/lo split hoisted to fill time; inner loop = LDS.128 + HMMA only.
// 512 threads, 16 warps, warp tile 32x16. Fused softmax + top-2 epilogue.
// Output (fp32): [0,2T) top2 probs | [2T,4T) top2 indices | [4T,68T) probs.

#define TM 128
#define KC 32
#define NE 64
#define RS 68                     // row stride in floats (17 float4, odd -> conflict-free)
#define XS_FLOATS (TM * RS)       // 8704
#define WS_FLOATS (NE * RS)       // 4352
#define SMEM_BYTES ((XS_FLOATS + WS_FLOATS) * 4)   // 52224

__device__ __forceinline__ float tf32f(float v) {
    uint32_t h;
    asm("cvt.rna.tf32.f32 %0, %1;" : "=r"(h) : "f"(v));
    return __uint_as_float(h);
}

__device__ __forceinline__ void mma_tf32(float* d, const uint32_t* a, const uint32_t* b) {
    asm volatile(
        "mma.sync.aligned.m16n8k8.row.col.f32.tf32.tf32.f32 "
        "{%0,%1,%2,%3}, {%4,%5,%6,%7}, {%8,%9}, {%0,%1,%2,%3};"
        : "+f"(d[0]), "+f"(d[1]), "+f"(d[2]), "+f"(d[3])
        : "r"(a[0]), "r"(a[1]), "r"(a[2]), "r"(a[3]), "r"(b[0]), "r"(b[1]));
}

// Store one loaded float4 (4 consecutive k of one row) into the packed
// fragment layout: entry (s8*4+tg) holds {hi(tg),hi(tg+4),lo(tg),lo(tg+4)}.
// base = row*RS + s8*16 + h   (h selects hi-component 0/1; lo at +2)
__device__ __forceinline__ void split_store(float* base, float4 v) {
    float h0 = tf32f(v.x), h1 = tf32f(v.y), h2 = tf32f(v.z), h3 = tf32f(v.w);
    base[0]      = h0;        base[4]      = h1;
    base[8]      = h2;        base[12]     = h3;
    base[0 + 2]  = v.x - h0;  base[4 + 2]  = v.y - h1;
    base[8 + 2]  = v.z - h2;  base[12 + 2] = v.w - h3;
}

__global__ __launch_bounds__(512, 1)
void moe_router_kernel(const float* __restrict__ x,
                       const float* __restrict__ w,
                       float* __restrict__ out_p,
                       float* __restrict__ out_i,
                       float* __restrict__ probs,
                       int D) {
    extern __shared__ __align__(16) float sm[];
    float* xs = sm;                   // [128][68] packed frag layout
    float* ws = sm + XS_FLOATS;       // [64][68]

    const int tid = threadIdx.x;
    const int wid = tid >> 5, lane = tid & 31;
    const int g = lane >> 2, tg = lane & 3;
    const int wm = wid & 3;           // token group: wm*32 .. +31
    const int wn = wid >> 2;          // expert group: wn*16 .. +15
    const long long tBase = (long long)blockIdx.x * TM;

    // fill roles
    const int xr = tid >> 2, xc = tid & 3;          // x: row 0..127, two f4 (k=4xc, 16+4xc)
    const int wr = tid >> 3, wc = tid & 7;          // w: row 0..63, one f4 (k=4wc)
    const float* xg = x + (tBase + xr) * (long long)D + 4 * xc;
    const float* wg = w + (long long)wr * D + 4 * wc;

    float* xdst0 = xs + xr * RS + (xc >> 1) * 16 + (xc & 1);
    float* xdst1 = xdst0 + 32;                       // s8 += 2
    float* wdst  = ws + wr * RS + (wc >> 1) * 16 + (wc & 1);

    float acc[2][2][4];
#pragma unroll
    for (int mt = 0; mt < 2; mt++)
#pragma unroll
        for (int nt = 0; nt < 2; nt++)
#pragma unroll
            for (int q = 0; q < 4; q++) acc[mt][nt][q] = 0.f;

    // compute-side fragment pointers (float4 units, row stride 17)
    const float4* ap = (const float4*)xs + (wm * 32 + g) * 17 + tg;
    const float4* bp = (const float4*)ws + (wn * 16 + g) * 17 + tg;

    float4 rx0, rx1, rw0;
    rx0 = *(const float4*)(xg);
    rx1 = *(const float4*)(xg + 16);
    rw0 = *(const float4*)(wg);

    const int nCh = D / KC;
    for (int i = 0; i < nCh; i++) {
        split_store(xdst0, rx0);
        split_store(xdst1, rx1);
        split_store(wdst, rw0);
        __syncthreads();

        if (i + 1 < nCh) {
            const float* xn = xg + (i + 1) * KC;
            const float* wn2 = wg + (i + 1) * KC;
            rx0 = *(const float4*)(xn);
            rx1 = *(const float4*)(xn + 16);
            rw0 = *(const float4*)(wn2);
        }

#pragma unroll
        for (int s8 = 0; s8 < 4; s8++) {
            const int o = s8 * 4;
            float4 fa0 = ap[o];                 // row g       (mt 0)
            float4 fa1 = ap[8 * 17 + o];        // row g+8
            float4 fa2 = ap[16 * 17 + o];       // row g+16    (mt 1)
            float4 fa3 = ap[24 * 17 + o];       // row g+24
            float4 fb0 = bp[o];                 // expert g    (nt 0)
            float4 fb1 = bp[8 * 17 + o];        // expert g+8  (nt 1)

            uint32_t ah0[4] = {__float_as_uint(fa0.x), __float_as_uint(fa1.x),
                               __float_as_uint(fa0.y), __float_as_uint(fa1.y)};
            uint32_t al0[4] = {__float_as_uint(fa0.z), __float_as_uint(fa1.z),
                               __float_as_uint(fa0.w), __float_as_uint(fa1.w)};
            uint32_t ah1[4] = {__float_as_uint(fa2.x), __float_as_uint(fa3.x),
                               __float_as_uint(fa2.y), __float_as_uint(fa3.y)};
            uint32_t al1[4] = {__float_as_uint(fa2.z), __float_as_uint(fa3.z),
                               __float_as_uint(fa2.w), __float_as_uint(fa3.w)};
            uint32_t bh0[2] = {__float_as_uint(fb0.x), __float_as_uint(fb0.y)};
            uint32_t bl0[2] = {__float_as_uint(fb0.z), __float_as_uint(fb0.w)};
            uint32_t bh1[2] = {__float_as_uint(fb1.x), __float_as_uint(fb1.y)};
            uint32_t bl1[2] = {__float_as_uint(fb1.z), __float_as_uint(fb1.w)};

            mma_tf32(acc[0][0], al0, bh0);
            mma_tf32(acc[0][0], ah0, bl0);
            mma_tf32(acc[0][0], ah0, bh0);
            mma_tf32(acc[0][1], al0, bh1);
            mma_tf32(acc[0][1], ah0, bl1);
            mma_tf32(acc[0][1], ah0, bh1);
            mma_tf32(acc[1][0], al1, bh0);
            mma_tf32(acc[1][0], ah1, bl0);
            mma_tf32(acc[1][0], ah1, bh0);
            mma_tf32(acc[1][1], al1, bh1);
            mma_tf32(acc[1][1], ah1, bl1);
            mma_tf32(acc[1][1], ah1, bh1);
        }
        __syncthreads();
    }

    // ---- epilogue: accums -> smem logits [128][68] ----
    float* lg = sm;
#pragma unroll
    for (int mt = 0; mt < 2; mt++)
#pragma unroll
        for (int nt = 0; nt < 2; nt++) {
            const int row = wm * 32 + mt * 16 + g;
            const int col = wn * 16 + nt * 8 + 2 * tg;
            *(float2*)&lg[row * RS + col] = make_float2(acc[mt][nt][0], acc[mt][nt][1]);
            *(float2*)&lg[(row + 8) * RS + col] = make_float2(acc[mt][nt][2], acc[mt][nt][3]);
        }
    __syncthreads();

    // warps 0-3: one token per lane; softmax + top-2 in registers
    if (wid < 4) {
        const int tl = wid * 32 + lane;
        float* row = &lg[tl * RS];
        float e[64];
#pragma unroll
        for (int c = 0; c < 64; c += 4) {
            float4 v = *(const float4*)(row + c);
            e[c] = v.x; e[c + 1] = v.y; e[c + 2] = v.z; e[c + 3] = v.w;
        }
        float m = e[0];
#pragma unroll
        for (int c = 1; c < 64; c++) m = fmaxf(m, e[c]);
        float sum = 0.f;
#pragma unroll
        for (int c = 0; c < 64; c++) { e[c] = __expf(e[c] - m); sum += e[c]; }
        float a1 = -1.f, a2 = -1.f;
        int i1 = 0, i2 = 0;
#pragma unroll
        for (int c = 0; c < 64; c++) {
            float p = e[c];
            if (p > a1)      { a2 = a1; i2 = i1; a1 = p; i1 = c; }
            else if (p > a2) { a2 = p; i2 = c; }
        }
        const float inv = 1.0f / sum;
#pragma unroll
        for (int c = 0; c < 64; c += 4)
            *(float4*)(row + c) = make_float4(e[c] * inv, e[c + 1] * inv,
                                              e[c + 2] * inv, e[c + 3] * inv);
        const long long t = tBase + tl;
        const float sn = a1 + a2;
        *(float2*)(out_p + t * 2) = make_float2(a1 / sn, a2 / sn);
        *(float2*)(out_i + t * 2) = make_float2((float)i1, (float)i2);
    }
    __syncthreads();

    // coalesced probs writeback: 2048 float4 per CTA, 512 threads
    {
        float* pg = probs + tBase * 64;
#pragma unroll
        for (int j = 0; j < 4; j++) {
            const int fidx = tid + 512 * j;
            const int trow = fidx >> 4, cc = fidx & 15;
            *(float4*)(pg + (long long)fidx * 4) = *(const float4*)&lg[trow * RS + cc * 4];
        }
    }
}

extern "C" void kernel_launch(void* const* d_in, const int* in_sizes, int n_in,
                              void* d_out, int out_size) {
    const float* x = (const float*)d_in[0];
    const float* w = (const float*)d_in[1];
    float* out = (float*)d_out;

    const long long T = (long long)out_size / 68;
    const int D = (int)((long long)in_sizes[0] / T);

    float* out_p = out;           // [T,2]
    float* out_i = out + 2 * T;   // [T,2]
    float* probs = out + 4 * T;   // [T,64]

    cudaFuncSetAttribute(moe_router_kernel,
                         cudaFuncAttributeMaxDynamicSharedMemorySize, SMEM_BYTES);
    moe_router_kernel<<<(int)(T / TM), 512, SMEM_BYTES>>>(x, w, out_p, out_i, probs, D);
}

// round 15
// speedup vs baseline: 1.3900x; 1.3900x over previous
#include <cuda_runtime.h>
#include <cstdint>

// MoE router: logits = x @ W^T via mma.sync tf32 3-term split (3xTF32).
// R9 structure (scalar conflict-free LDS) at TM=64 / 2 CTAs-per-SM for latency cover.
// Output (fp32): [0,2T) top2 probs | [2T,4T) top2 indices | [4T,68T) probs.

#define TM 64           // tokens per CTA
#define KC 32           // K per chunk
#define NE 64           // experts
#define XS_S 36         // smem row stride (words): scalar frag reads conflict-free
#define LG_S 68         // logits row stride (words)

__device__ __forceinline__ uint32_t tf32_hi(float v) {
    uint32_t h;
    asm("cvt.rna.tf32.f32 %0, %1;" : "=r"(h) : "f"(v));
    return h;
}

__device__ __forceinline__ void mma_tf32(float* d, const uint32_t* a, const uint32_t* b) {
    asm volatile(
        "mma.sync.aligned.m16n8k8.row.col.f32.tf32.tf32.f32 "
        "{%0,%1,%2,%3}, {%4,%5,%6,%7}, {%8,%9}, {%0,%1,%2,%3};"
        : "+f"(d[0]), "+f"(d[1]), "+f"(d[2]), "+f"(d[3])
        : "r"(a[0]), "r"(a[1]), "r"(a[2]), "r"(a[3]), "r"(b[0]), "r"(b[1]));
}

__global__ __launch_bounds__(256, 2)
void moe_router_kernel(const float* __restrict__ x,
                       const float* __restrict__ w,
                       float* __restrict__ out_p,
                       float* __restrict__ out_i,
                       float* __restrict__ probs,
                       int D) {
    __shared__ __align__(16) float sm[2 * TM * XS_S];   // xs[64][36] | ws[64][36]
    float* xs = sm;
    float* ws = sm + TM * XS_S;

    const int tid = threadIdx.x;
    const int wid = tid >> 5, lane = tid & 31;
    const int g = lane >> 2, tg = lane & 3;
    const int wm = wid & 1;          // token group: wm*32 .. +31
    const int wn = wid >> 1;         // expert group: wn*16 .. +15
    const long long tBase = (long long)blockIdx.x * TM;

    // fill roles: 4 threads per row, each 8 consecutive k (two float4)
    const int fr = tid >> 2, fk = (tid & 3) * 8;
    const float* xg = x + (tBase + fr) * (long long)D + fk;
    const float* wg = w + (long long)fr * D + fk;
    float* xdst = &xs[fr * XS_S + fk];
    float* wdst = &ws[fr * XS_S + fk];

    float acc[2][2][4];
#pragma unroll
    for (int mt = 0; mt < 2; mt++)
#pragma unroll
        for (int nt = 0; nt < 2; nt++)
#pragma unroll
            for (int q = 0; q < 4; q++) acc[mt][nt][q] = 0.f;

    float4 rx0 = *(const float4*)(xg);
    float4 rx1 = *(const float4*)(xg + 4);
    float4 rw0 = *(const float4*)(wg);
    float4 rw1 = *(const float4*)(wg + 4);

    const int nCh = D / KC;
    for (int i = 0; i < nCh; i++) {
        *(float4*)(xdst)     = rx0;
        *(float4*)(xdst + 4) = rx1;
        *(float4*)(wdst)     = rw0;
        *(float4*)(wdst + 4) = rw1;
        __syncthreads();

        if (i + 1 < nCh) {
            const float* xn = xg + (i + 1) * KC;
            const float* wn2 = wg + (i + 1) * KC;
            rx0 = *(const float4*)(xn);
            rx1 = *(const float4*)(xn + 4);
            rw0 = *(const float4*)(wn2);
            rw1 = *(const float4*)(wn2 + 4);
        }

#pragma unroll
        for (int s8 = 0; s8 < 4; s8++) {
            const int kb = 8 * s8;
            uint32_t ah[2][4], al[2][4], bh[2][2], bl[2][2];
#pragma unroll
            for (int mt = 0; mt < 2; mt++) {
                const int t0 = wm * 32 + mt * 16;
                float v0 = xs[(t0 + g) * XS_S + kb + tg];
                float v1 = xs[(t0 + g + 8) * XS_S + kb + tg];
                float v2 = xs[(t0 + g) * XS_S + kb + tg + 4];
                float v3 = xs[(t0 + g + 8) * XS_S + kb + tg + 4];
                ah[mt][0] = tf32_hi(v0); al[mt][0] = __float_as_uint(v0 - __uint_as_float(ah[mt][0]));
                ah[mt][1] = tf32_hi(v1); al[mt][1] = __float_as_uint(v1 - __uint_as_float(ah[mt][1]));
                ah[mt][2] = tf32_hi(v2); al[mt][2] = __float_as_uint(v2 - __uint_as_float(ah[mt][2]));
                ah[mt][3] = tf32_hi(v3); al[mt][3] = __float_as_uint(v3 - __uint_as_float(ah[mt][3]));
            }
#pragma unroll
            for (int nt = 0; nt < 2; nt++) {
                const int e0 = wn * 16 + nt * 8 + g;
                float u0 = ws[e0 * XS_S + kb + tg];
                float u1 = ws[e0 * XS_S + kb + tg + 4];
                bh[nt][0] = tf32_hi(u0); bl[nt][0] = __float_as_uint(u0 - __uint_as_float(bh[nt][0]));
                bh[nt][1] = tf32_hi(u1); bl[nt][1] = __float_as_uint(u1 - __uint_as_float(bh[nt][1]));
            }
#pragma unroll
            for (int mt = 0; mt < 2; mt++)
#pragma unroll
                for (int nt = 0; nt < 2; nt++) {
                    mma_tf32(acc[mt][nt], al[mt], bh[nt]);
                    mma_tf32(acc[mt][nt], ah[mt], bl[nt]);
                    mma_tf32(acc[mt][nt], ah[mt], bh[nt]);
                }
        }
        __syncthreads();
    }

    // ---- epilogue: accums -> smem logits [64][68] ----
    float* lg = sm;
#pragma unroll
    for (int mt = 0; mt < 2; mt++)
#pragma unroll
        for (int nt = 0; nt < 2; nt++) {
            const int row = wm * 32 + mt * 16 + g;
            const int col = wn * 16 + nt * 8 + 2 * tg;
            *(float2*)&lg[row * LG_S + col] = make_float2(acc[mt][nt][0], acc[mt][nt][1]);
            *(float2*)&lg[(row + 8) * LG_S + col] = make_float2(acc[mt][nt][2], acc[mt][nt][3]);
        }
    __syncthreads();

    // warps 0-1: one token per lane; softmax + top-2 in registers
    if (wid < 2) {
        const int tl = wid * 32 + lane;
        float* row = &lg[tl * LG_S];
        float e[64];
#pragma unroll
        for (int c = 0; c < 64; c += 4) {
            float4 v = *(const float4*)(row + c);
            e[c] = v.x; e[c + 1] = v.y; e[c + 2] = v.z; e[c + 3] = v.w;
        }
        float m = e[0];
#pragma unroll
        for (int c = 1; c < 64; c++) m = fmaxf(m, e[c]);
        float sum = 0.f;
#pragma unroll
        for (int c = 0; c < 64; c++) { e[c] = __expf(e[c] - m); sum += e[c]; }
        float a1 = -1.f, a2 = -1.f;
        int i1 = 0, i2 = 0;
#pragma unroll
        for (int c = 0; c < 64; c++) {
            float p = e[c];
            if (p > a1)      { a2 = a1; i2 = i1; a1 = p; i1 = c; }
            else if (p > a2) { a2 = p; i2 = c; }
        }
        const float inv = 1.0f / sum;
#pragma unroll
        for (int c = 0; c < 64; c += 4)
            *(float4*)(row + c) = make_float4(e[c] * inv, e[c + 1] * inv,
                                              e[c + 2] * inv, e[c + 3] * inv);
        const long long t = tBase + tl;
        const float sn = a1 + a2;
        *(float2*)(out_p + t * 2) = make_float2(a1 / sn, a2 / sn);
        *(float2*)(out_i + t * 2) = make_float2((float)i1, (float)i2);
    }
    __syncthreads();

    // coalesced probs writeback: 1024 float4 per CTA, 256 threads
    {
        float* pg = probs + tBase * 64;
#pragma unroll
        for (int j = 0; j < 4; j++) {
            const int fidx = tid + 256 * j;
            const int trow = fidx >> 4, cc = fidx & 15;
            *(float4*)(pg + (long long)fidx * 4) = *(const float4*)&lg[trow * LG_S + cc * 4];
        }
    }
}

extern "C" void kernel_launch(void* const* d_in, const int* in_sizes, int n_in,
                              void* d_out, int out_size) {
    const float* x = (const float*)d_in[0];
    const float* w = (const float*)d_in[1];
    float* out = (float*)d_out;

    const long long T = (long long)out_size / 68;
    const int D = (int)((long long)in_sizes[0] / T);

    float* out_p = out;           // [T,2]
    float* out_i = out + 2 * T;   // [T,2]
    float* probs = out + 4 * T;   // [T,64]

    moe_router_kernel<<<(int)(T / TM), 256>>>(x, w, out_p, out_i, probs, D);
}

// round 16
// speedup vs baseline: 1.5470x; 1.1129x over previous
#include <cuda_runtime.h>
#include <cstdint>

// MoE router: logits = x @ W^T via mma.sync tf32 3-term split (3xTF32).
// hi/lo split hoisted to FILL time into separate scalar-layout tiles;
// inner loop = conflict-free scalar LDS + HMMA only. TM=128, 8 warps, 2 CTAs/SM.
// Output (fp32): [0,2T) top2 probs | [2T,4T) top2 indices | [4T,68T) probs.

#define TM 128
#define KC 32
#define NE 64
#define TS 36                       // tile row stride (words) -> scalar reads 1-phase
#define LG_S 68                     // logits row stride (words)

// float offsets of the four tiles
#define XH_OFF 0
#define XL_OFF (TM * TS)            // 4608
#define WH_OFF (2 * TM * TS)        // 9216
#define WL_OFF (2 * TM * TS + NE * TS)  // 11520
#define SM_FLOATS (2 * TM * TS + 2 * NE * TS)   // 13824
#define SMEM_BYTES (SM_FLOATS * 4)              // 55296

__device__ __forceinline__ float tf32f(float v) {
    uint32_t h;
    asm("cvt.rna.tf32.f32 %0, %1;" : "=r"(h) : "f"(v));
    return __uint_as_float(h);
}

__device__ __forceinline__ void mma_tf32(float* d, const uint32_t* a, const uint32_t* b) {
    asm volatile(
        "mma.sync.aligned.m16n8k8.row.col.f32.tf32.tf32.f32 "
        "{%0,%1,%2,%3}, {%4,%5,%6,%7}, {%8,%9}, {%0,%1,%2,%3};"
        : "+f"(d[0]), "+f"(d[1]), "+f"(d[2]), "+f"(d[3])
        : "r"(a[0]), "r"(a[1]), "r"(a[2]), "r"(a[3]), "r"(b[0]), "r"(b[1]));
}

__device__ __forceinline__ void split4(float* hd, float* ld, float4 v) {
    float h0 = tf32f(v.x), h1 = tf32f(v.y), h2 = tf32f(v.z), h3 = tf32f(v.w);
    *(float4*)hd = make_float4(h0, h1, h2, h3);
    *(float4*)ld = make_float4(v.x - h0, v.y - h1, v.z - h2, v.w - h3);
}

__global__ __launch_bounds__(256, 2)
void moe_router_kernel(const float* __restrict__ x,
                       const float* __restrict__ w,
                       float* __restrict__ out_p,
                       float* __restrict__ out_i,
                       float* __restrict__ probs,
                       int D) {
    extern __shared__ __align__(16) float sm[];
    float* xh = sm + XH_OFF;
    float* xl = sm + XL_OFF;
    float* wh = sm + WH_OFF;
    float* wl = sm + WL_OFF;

    const int tid = threadIdx.x;
    const int wid = tid >> 5, lane = tid & 31;
    const int g = lane >> 2, tg = lane & 3;
    const int wm = wid & 3;            // token group: wm*32 .. +31
    const int wn = wid >> 2;           // expert group: wn*32 .. +31
    const long long tBase = (long long)blockIdx.x * TM;

    // fill roles
    const int xr = tid >> 1, xk = (tid & 1) * 16;   // x: row 0..127, 16 consecutive k
    const int wr = tid >> 2, wk = (tid & 3) * 8;    // w: row 0..63,  8 consecutive k
    const float* xg = x + (tBase + xr) * (long long)D + xk;
    const float* wg = w + (long long)wr * D + wk;
    float* xhd = xh + xr * TS + xk;
    float* xld = xl + xr * TS + xk;
    float* whd = wh + wr * TS + wk;
    float* wld = wl + wr * TS + wk;

    float acc[2][4][4];
#pragma unroll
    for (int mt = 0; mt < 2; mt++)
#pragma unroll
        for (int nt = 0; nt < 4; nt++)
#pragma unroll
            for (int q = 0; q < 4; q++) acc[mt][nt][q] = 0.f;

    float4 rx[4], rw[2];
#pragma unroll
    for (int j = 0; j < 4; j++) rx[j] = *(const float4*)(xg + 4 * j);
#pragma unroll
    for (int j = 0; j < 2; j++) rw[j] = *(const float4*)(wg + 4 * j);

    const int nCh = D / KC;
    for (int i = 0; i < nCh; i++) {
#pragma unroll
        for (int j = 0; j < 4; j++) split4(xhd + 4 * j, xld + 4 * j, rx[j]);
#pragma unroll
        for (int j = 0; j < 2; j++) split4(whd + 4 * j, wld + 4 * j, rw[j]);
        __syncthreads();

        if (i + 1 < nCh) {
            const float* xn = xg + (i + 1) * KC;
            const float* wn2 = wg + (i + 1) * KC;
#pragma unroll
            for (int j = 0; j < 4; j++) rx[j] = *(const float4*)(xn + 4 * j);
#pragma unroll
            for (int j = 0; j < 2; j++) rw[j] = *(const float4*)(wn2 + 4 * j);
        }

#pragma unroll
        for (int s8 = 0; s8 < 4; s8++) {
            const int kb = 8 * s8;
            uint32_t ah[2][4], al[2][4], bh[4][2], bl[4][2];
#pragma unroll
            for (int mt = 0; mt < 2; mt++) {
                const int r0 = (wm * 32 + mt * 16 + g) * TS + kb + tg;
                const int r1 = r0 + 8 * TS;
                ah[mt][0] = __float_as_uint(xh[r0]);
                ah[mt][1] = __float_as_uint(xh[r1]);
                ah[mt][2] = __float_as_uint(xh[r0 + 4]);
                ah[mt][3] = __float_as_uint(xh[r1 + 4]);
                al[mt][0] = __float_as_uint(xl[r0]);
                al[mt][1] = __float_as_uint(xl[r1]);
                al[mt][2] = __float_as_uint(xl[r0 + 4]);
                al[mt][3] = __float_as_uint(xl[r1 + 4]);
            }
#pragma unroll
            for (int nt = 0; nt < 4; nt++) {
                const int e0 = (wn * 32 + nt * 8 + g) * TS + kb + tg;
                bh[nt][0] = __float_as_uint(wh[e0]);
                bh[nt][1] = __float_as_uint(wh[e0 + 4]);
                bl[nt][0] = __float_as_uint(wl[e0]);
                bl[nt][1] = __float_as_uint(wl[e0 + 4]);
            }
#pragma unroll
            for (int mt = 0; mt < 2; mt++)
#pragma unroll
                for (int nt = 0; nt < 4; nt++) {
                    mma_tf32(acc[mt][nt], al[mt], bh[nt]);
                    mma_tf32(acc[mt][nt], ah[mt], bl[nt]);
                    mma_tf32(acc[mt][nt], ah[mt], bh[nt]);
                }
        }
        __syncthreads();
    }

    // ---- epilogue: accums -> smem logits [128][68] ----
    float* lg = sm;
#pragma unroll
    for (int mt = 0; mt < 2; mt++)
#pragma unroll
        for (int nt = 0; nt < 4; nt++) {
            const int row = wm * 32 + mt * 16 + g;
            const int col = wn * 32 + nt * 8 + 2 * tg;
            *(float2*)&lg[row * LG_S + col] = make_float2(acc[mt][nt][0], acc[mt][nt][1]);
            *(float2*)&lg[(row + 8) * LG_S + col] = make_float2(acc[mt][nt][2], acc[mt][nt][3]);
        }
    __syncthreads();

    // warps 0-3: one token per lane; softmax + top-2 in registers
    if (wid < 4) {
        const int tl = wid * 32 + lane;
        float* row = &lg[tl * LG_S];
        float e[64];
#pragma unroll
        for (int c = 0; c < 64; c += 4) {
            float4 v = *(const float4*)(row + c);
            e[c] = v.x; e[c + 1] = v.y; e[c + 2] = v.z; e[c + 3] = v.w;
        }
        float m = e[0];
#pragma unroll
        for (int c = 1; c < 64; c++) m = fmaxf(m, e[c]);
        float sum = 0.f;
#pragma unroll
        for (int c = 0; c < 64; c++) { e[c] = __expf(e[c] - m); sum += e[c]; }
        float a1 = -1.f, a2 = -1.f;
        int i1 = 0, i2 = 0;
#pragma unroll
        for (int c = 0; c < 64; c++) {
            float p = e[c];
            if (p > a1)      { a2 = a1; i2 = i1; a1 = p; i1 = c; }
            else if (p > a2) { a2 = p; i2 = c; }
        }
        const float inv = 1.0f / sum;
#pragma unroll
        for (int c = 0; c < 64; c += 4)
            *(float4*)(row + c) = make_float4(e[c] * inv, e[c + 1] * inv,
                                              e[c + 2] * inv, e[c + 3] * inv);
        const long long t = tBase + tl;
        const float sn = a1 + a2;
        *(float2*)(out_p + t * 2) = make_float2(a1 / sn, a2 / sn);
        *(float2*)(out_i + t * 2) = make_float2((float)i1, (float)i2);
    }
    __syncthreads();

    // coalesced probs writeback: 2048 float4 per CTA, 256 threads
    {
        float* pg = probs + tBase * 64;
#pragma unroll
        for (int j = 0; j < 8; j++) {
            const int fidx = tid + 256 * j;
            const int trow = fidx >> 4, cc = fidx & 15;
            *(float4*)(pg + (long long)fidx * 4) = *(const float4*)&lg[trow * LG_S + cc * 4];
        }
    }
}

extern "C" void kernel_launch(void* const* d_in, const int* in_sizes, int n_in,
                              void* d_out, int out_size) {
    const float* x = (const float*)d_in[0];
    const float* w = (const float*)d_in[1];
    float* out = (float*)d_out;

    const long long T = (long long)out_size / 68;
    const int D = (int)((long long)in_sizes[0] / T);

    float* out_p = out;           // [T,2]
    float* out_i = out + 2 * T;   // [T,2]
    float* probs = out + 4 * T;   // [T,64]

    cudaFuncSetAttribute(moe_router_kernel,
                         cudaFuncAttributeMaxDynamicSharedMemorySize, SMEM_BYTES);
    moe_router_kernel<<<(int)(T / TM), 256, SMEM_BYTES>>>(x, w, out_p, out_i, probs, D);
}